// round 10
// baseline (speedup 1.0000x reference)
#include <cuda_runtime.h>
#include <cstdint>

#define J   17
#define E   4096
#define M16 16
#define K1  (2*E)       // 8192
#define K2  E           // 4096
#define TK1 128         // GEMM1: 64 slabs, grid (8,64)
#define TK2 64          // GEMM2: 64 slabs, grid (8,64)
#define KS  64
#define NRBLK 128       // reduce_apply grid size (single wave)
#define LN_EPS 1e-5f

typedef unsigned long long ull;

// -------- device scratch --------
__device__ float    d_h[M16 * E];             // 256 KB hidden
__device__ float    d_partial[KS * M16 * E];  // 16 MB
__device__ float2   d_stats[M16 * 8];         // per-(row,chunk) sum/sumsq
__device__ unsigned d_ctr[2];                 // grid-sync counters

__device__ __forceinline__ void fma2(ull& d, ull a, ull b) {
    asm("fma.rn.f32x2 %0, %1, %2, %0;" : "+l"(d) : "l"(a), "l"(b));
}
__device__ __forceinline__ ull dup_pack(float p) {
    unsigned int u = __float_as_uint(p);
    return ((ull)u << 32) | (ull)u;
}

// ============================================================
// L2-normalize joints (scale sqrt(E)=64) + zero sync counters.
// grid=17, block=256.
// ============================================================
__global__ void __launch_bounds__(256) normalize_kernel(
    const float* __restrict__ x, float* __restrict__ out_joint)
{
    if (blockIdx.x == 0 && threadIdx.x < 2) d_ctr[threadIdx.x] = 0u;

    int row = blockIdx.x;
    int tid = threadIdx.x;
    const float4* xr4 = reinterpret_cast<const float4*>(x + (size_t)row * E);

    float4 v[4];
    float s = 0.f;
    #pragma unroll
    for (int i = 0; i < 4; i++) {
        v[i] = xr4[tid + i * 256];
        s += v[i].x * v[i].x + v[i].y * v[i].y
           + v[i].z * v[i].z + v[i].w * v[i].w;
    }
    __shared__ float red[256];
    red[tid] = s;
    __syncthreads();
    for (int off = 128; off > 0; off >>= 1) {
        if (tid < off) red[tid] += red[tid + off];
        __syncthreads();
    }
    __shared__ float s_inv;
    if (tid == 0) s_inv = 64.0f / fmaxf(sqrtf(red[0]), 1e-12f);
    __syncthreads();
    float inv = s_inv;
    float4* o4 = reinterpret_cast<float4*>(out_joint + (size_t)row * E);
    #pragma unroll
    for (int i = 0; i < 4; i++) {
        float4 y;
        y.x = v[i].x * inv; y.y = v[i].y * inv;
        y.z = v[i].z * inv; y.w = v[i].w * inv;
        o4[tid + i * 256] = y;
    }
}

// ============================================================
// Split-K GEMM, 2 cols/thread, 4 CTAs/SM (32 warps) for latency hiding.
// out[m][n] = sum_k act[k][m] * W[k][n]
// grid=(8, K/TK), block=256. Double-buffered W prefetch (4 rows/chunk).
// MODE 0: gather pairs from joint+bone_pairs; MODE 1: from linear h.
// ============================================================
template<int TK, int MODE>
__global__ void __launch_bounds__(256, 4) gemm_splitk(
    const float* __restrict__ W,
    const float* __restrict__ act,
    const int*   __restrict__ bp,
    float* __restrict__ partial)
{
    __shared__ ull sp[TK * M16];

    int tid = threadIdx.x;
    int k0 = blockIdx.y * TK;

    {
        int m = tid & 15;
        const float* r0;
        const float* r1;
        if (MODE == 0) {
            r0 = act + (size_t)bp[2 * m] * E;
            r1 = act + (size_t)bp[2 * m + 1] * E;
        } else {
            r0 = act + (size_t)m * E;
            r1 = r0;
        }
        #pragma unroll
        for (int i = 0; i < (TK * M16) / 256; i++) {
            int kl = (tid >> 4) + i * 16;
            int k = k0 + kl;
            float p;
            if (MODE == 0) {
                int col = k & (E - 1);
                p = (k < E) ? r0[col] : r1[col];
            } else {
                p = r0[k];
            }
            sp[kl * M16 + m] = dup_pack(p);
        }
    }
    __syncthreads();

    int n = blockIdx.x * 512 + tid * 2;
    const float* wp = W + (size_t)k0 * E + n;

    ull acc[M16];
    #pragma unroll
    for (int m = 0; m < M16; m++) acc[m] = 0ULL;

    ull wv0[4], wv1[4];

    #pragma unroll
    for (int j = 0; j < 4; j++)
        wv0[j] = *reinterpret_cast<const ull*>(wp + (size_t)j * E);

    #define CONSUME(WV, KB)                                                   \
        _Pragma("unroll")                                                     \
        for (int j = 0; j < 4; j++) {                                         \
            const ulonglong2* row =                                           \
                reinterpret_cast<const ulonglong2*>(sp + ((KB) + j) * M16);   \
            _Pragma("unroll")                                                 \
            for (int q = 0; q < 8; q++) {                                     \
                ulonglong2 r = row[q];                                        \
                fma2(acc[2*q  ], WV[j], r.x);                                 \
                fma2(acc[2*q+1], WV[j], r.y);                                 \
            }                                                                 \
        }

    #pragma unroll 1
    for (int cb = 0; cb < TK - 8; cb += 8) {
        #pragma unroll
        for (int j = 0; j < 4; j++)
            wv1[j] = *reinterpret_cast<const ull*>(wp + (size_t)(cb + 4 + j) * E);
        CONSUME(wv0, cb)
        #pragma unroll
        for (int j = 0; j < 4; j++)
            wv0[j] = *reinterpret_cast<const ull*>(wp + (size_t)(cb + 8 + j) * E);
        CONSUME(wv1, cb + 4)
    }
    {
        const int cb = TK - 8;
        #pragma unroll
        for (int j = 0; j < 4; j++)
            wv1[j] = *reinterpret_cast<const ull*>(wp + (size_t)(cb + 4 + j) * E);
        CONSUME(wv0, cb)
        CONSUME(wv1, cb + 4)
    }
    #undef CONSUME

    size_t base = ((size_t)blockIdx.y * M16) * E + n;
    #pragma unroll
    for (int m = 0; m < M16; m++)
        *reinterpret_cast<float2*>(&partial[base + (size_t)m * E]) =
            *reinterpret_cast<float2*>(&acc[m]);
}

// ---- grid-wide sync (all NRBLK CTAs resident: grid < SM count) ----
__device__ __forceinline__ void grid_sync(unsigned* ctr) {
    __syncthreads();
    if (threadIdx.x == 0) {
        __threadfence();
        atomicAdd(ctr, 1u);
        while (atomicAdd(ctr, 0u) < (unsigned)NRBLK) { }
    }
    __syncthreads();
    __threadfence();
}

// ============================================================
// Fused split-K reduce + bias + LN (+ReLU) with internal grid sync.
// grid=(8, 16)=128 blocks, block=256. Pre-LN values stay in regs.
// ============================================================
template<bool RELU>
__global__ void __launch_bounds__(256) reduce_apply_kernel(
    const float4* __restrict__ partial4,
    const float4* __restrict__ bias4,
    const float4* __restrict__ gamma4,
    const float4* __restrict__ beta4,
    float4* __restrict__ out4,
    float2* __restrict__ stats,
    unsigned* ctr)
{
    int m    = blockIdx.y;
    int tid  = threadIdx.x;
    int c4   = tid & 127;
    int half = tid >> 7;
    int n4   = blockIdx.x * 128 + c4;

    const float4* p = partial4 + (size_t)m * (E / 4) + n4;
    const size_t stride = (size_t)M16 * (E / 4);

    float4 a[4];
    a[0] = (half == 0) ? bias4[n4] : make_float4(0.f, 0.f, 0.f, 0.f);
    #pragma unroll
    for (int r = 1; r < 4; r++) a[r] = make_float4(0.f, 0.f, 0.f, 0.f);

    int s0 = half * 32;
    #pragma unroll
    for (int ks = 0; ks < 32; ks += 4) {
        #pragma unroll
        for (int r = 0; r < 4; r++) {
            float4 v = __ldcs(&p[(size_t)(s0 + ks + r) * stride]);
            a[r].x += v.x; a[r].y += v.y; a[r].z += v.z; a[r].w += v.w;
        }
    }
    a[0].x += a[1].x; a[0].y += a[1].y; a[0].z += a[1].z; a[0].w += a[1].w;
    a[2].x += a[3].x; a[2].y += a[3].y; a[2].z += a[3].z; a[2].w += a[3].w;
    float4 v;
    v.x = a[0].x + a[2].x; v.y = a[0].y + a[2].y;
    v.z = a[0].z + a[2].z; v.w = a[0].w + a[2].w;

    __shared__ float4 buf[128];
    __shared__ float rs[128], rq[128];
    if (half == 1) buf[c4] = v;
    __syncthreads();
    if (half == 0) {
        float4 o = buf[c4];
        v.x += o.x; v.y += o.y; v.z += o.z; v.w += o.w;
        rs[c4] = (v.x + v.y) + (v.z + v.w);
        rq[c4] = (v.x * v.x + v.y * v.y) + (v.z * v.z + v.w * v.w);
    }
    __syncthreads();
    for (int off = 64; off > 0; off >>= 1) {
        if (tid < off) { rs[tid] += rs[tid + off]; rq[tid] += rq[tid + off]; }
        __syncthreads();
    }
    if (tid == 0)
        stats[m * 8 + blockIdx.x] = make_float2(rs[0], rq[0]);

    grid_sync(ctr);

    if (half == 0) {
        float sum = 0.f, sq = 0.f;
        #pragma unroll
        for (int c = 0; c < 8; c++) {
            float2 s = __ldcg(&stats[m * 8 + c]);
            sum += s.x; sq += s.y;
        }
        float mu   = sum * (1.0f / E);
        float var  = sq * (1.0f / E) - mu * mu;
        float rstd = rsqrtf(var + LN_EPS);

        float4 g = gamma4[n4];
        float4 b = beta4[n4];
        float4 y;
        y.x = (v.x - mu) * rstd * g.x + b.x;
        y.y = (v.y - mu) * rstd * g.y + b.y;
        y.z = (v.z - mu) * rstd * g.z + b.z;
        y.w = (v.w - mu) * rstd * g.w + b.w;
        if (RELU) {
            y.x = fmaxf(y.x, 0.f); y.y = fmaxf(y.y, 0.f);
            y.z = fmaxf(y.z, 0.f); y.w = fmaxf(y.w, 0.f);
        }
        out4[(size_t)m * (E / 4) + n4] = y;
    }
}

// ============================================================
// launcher — 5 launches
// ============================================================
extern "C" void kernel_launch(void* const* d_in, const int* in_sizes, int n_in,
                              void* d_out, int out_size)
{
    const float* emb = (const float*)d_in[0];
    const float* W1  = (const float*)d_in[1];
    const float* b1  = (const float*)d_in[2];
    const float* g1  = (const float*)d_in[3];
    const float* be1 = (const float*)d_in[4];
    const float* W2  = (const float*)d_in[5];
    const float* b2  = (const float*)d_in[6];
    const float* g2  = (const float*)d_in[7];
    const float* be2 = (const float*)d_in[8];
    const int*   bp  = (const int*)d_in[9];

    float* out = (float*)d_out;
    float* out_joint = out;                      // [17][4096]
    float* out_bone  = out + (size_t)J * E;      // [16][4096]

    float*    h_p;       cudaGetSymbolAddress((void**)&h_p, d_h);
    float*    partial_p; cudaGetSymbolAddress((void**)&partial_p, d_partial);
    float2*   stats_p;   cudaGetSymbolAddress((void**)&stats_p, d_stats);
    unsigned* ctr_p;     cudaGetSymbolAddress((void**)&ctr_p, d_ctr);

    // 1. normalize joints -> output head (+ zero sync counters)
    normalize_kernel<<<J, 256>>>(emb, out_joint);

    // 2. GEMM1 (pair gather fused)
    gemm_splitk<TK1, 0><<<dim3(8, K1 / TK1), 256>>>(
        W1, out_joint, bp, partial_p);

    // 3. fused reduce + LN + ReLU -> h
    reduce_apply_kernel<true><<<dim3(8, M16), 256>>>(
        (const float4*)partial_p, (const float4*)b1,
        (const float4*)g1, (const float4*)be1,
        (float4*)h_p, stats_p, ctr_p + 0);

    // 4. GEMM2 (h gather fused)
    gemm_splitk<TK2, 1><<<dim3(8, K2 / TK2), 256>>>(
        W2, h_p, nullptr, partial_p);

    // 5. fused reduce + LN -> bone features
    reduce_apply_kernel<false><<<dim3(8, M16), 256>>>(
        (const float4*)partial_p, (const float4*)b2,
        (const float4*)g2, (const float4*)be2,
        (float4*)out_bone, stats_p, ctr_p + 1);
}

// round 12
// speedup vs baseline: 2.8686x; 2.8686x over previous
#include <cuda_runtime.h>
#include <cstdint>

#define J   17
#define E   4096
#define M16 16
#define K1  (2*E)       // 8192
#define K2  E           // 4096
#define TK1 128         // GEMM1: 64 slabs, grid (4,64)
#define TK2 64          // GEMM2: 64 slabs, grid (4,64)
#define KS  64
#define NRBLK 128       // reduce_apply grid size (single wave)
#define LN_EPS 1e-5f
#define STG_BYTES 32768 // one W stage: 8 rows x 1024 cols x 4B
#define NSTAGES 3

typedef unsigned long long ull;

// -------- device scratch --------
__device__ float    d_h[M16 * E];             // 256 KB hidden
__device__ float    d_partial[KS * M16 * E];  // 16 MB
__device__ float2   d_stats[M16 * 8];         // per-(row,chunk) sum/sumsq
__device__ unsigned d_ctr[2];                 // grid-sync counters

__device__ __forceinline__ void fma2(ull& d, ull a, ull b) {
    asm("fma.rn.f32x2 %0, %1, %2, %0;" : "+l"(d) : "l"(a), "l"(b));
}
__device__ __forceinline__ ull dup_pack(float p) {
    unsigned int u = __float_as_uint(p);
    return ((ull)u << 32) | (ull)u;
}

// ============================================================
// L2-normalize joints (scale sqrt(E)=64) + zero sync counters.
// ============================================================
__global__ void __launch_bounds__(256) normalize_kernel(
    const float* __restrict__ x, float* __restrict__ out_joint)
{
    if (blockIdx.x == 0 && threadIdx.x < 2) d_ctr[threadIdx.x] = 0u;

    int row = blockIdx.x;
    int tid = threadIdx.x;
    const float4* xr4 = reinterpret_cast<const float4*>(x + (size_t)row * E);

    float4 v[4];
    float s = 0.f;
    #pragma unroll
    for (int i = 0; i < 4; i++) {
        v[i] = xr4[tid + i * 256];
        s += v[i].x * v[i].x + v[i].y * v[i].y
           + v[i].z * v[i].z + v[i].w * v[i].w;
    }
    __shared__ float red[256];
    red[tid] = s;
    __syncthreads();
    for (int off = 128; off > 0; off >>= 1) {
        if (tid < off) red[tid] += red[tid + off];
        __syncthreads();
    }
    __shared__ float s_inv;
    if (tid == 0) s_inv = 64.0f / fmaxf(sqrtf(red[0]), 1e-12f);
    __syncthreads();
    float inv = s_inv;
    float4* o4 = reinterpret_cast<float4*>(out_joint + (size_t)row * E);
    #pragma unroll
    for (int i = 0; i < 4; i++) {
        float4 y;
        y.x = v[i].x * inv; y.y = v[i].y * inv;
        y.z = v[i].z * inv; y.w = v[i].w * inv;
        o4[tid + i * 256] = y;
    }
}

// ============================================================
// Split-K GEMM, 4 cols/thread, 2 CTAs/SM, cp.async 3-stage W pipeline.
// Each thread cp.asyncs exactly the 16B/row it consumes -> no barrier.
// grid=(4, K/TK), block=256. Dynamic smem: act slab + 3 W stages.
// MODE 0: gather pairs from joint+bone_pairs; MODE 1: from linear h.
// ============================================================
template<int TK, int MODE>
__global__ void __launch_bounds__(256, 2) gemm_splitk(
    const float* __restrict__ W,
    const float* __restrict__ act,
    const int*   __restrict__ bp,
    float* __restrict__ partial)
{
    extern __shared__ char smem[];
    ull*  sp      = reinterpret_cast<ull*>(smem);       // TK*16 ull slab
    char* wstage  = smem + (size_t)TK * M16 * 8;        // 3 x 32KB stages

    int tid = threadIdx.x;
    int k0 = blockIdx.y * TK;

    // ---- activation slab fill (gather + duplicate) ----
    {
        int m = tid & 15;
        const float* r0;
        const float* r1;
        if (MODE == 0) {
            r0 = act + (size_t)bp[2 * m] * E;
            r1 = act + (size_t)bp[2 * m + 1] * E;
        } else {
            r0 = act + (size_t)m * E;
            r1 = r0;
        }
        #pragma unroll
        for (int i = 0; i < (TK * M16) / 256; i++) {
            int kl = (tid >> 4) + i * 16;
            int k = k0 + kl;
            float p;
            if (MODE == 0) {
                int col = k & (E - 1);
                p = (k < E) ? r0[col] : r1[col];
            } else {
                p = r0[k];
            }
            sp[kl * M16 + m] = dup_pack(p);
        }
    }

    int n = blockIdx.x * 1024 + tid * 4;
    const float* wp = W + (size_t)k0 * E + n;        // this thread's col base
    unsigned wsaddr =
        (unsigned)__cvta_generic_to_shared(wstage) + tid * 16;

    const int NSTG = TK / 8;                          // 8-row stages

    // ---- prologue: issue 3 stages ----
    #pragma unroll
    for (int s = 0; s < NSTAGES; s++) {
        if (s < NSTG) {
            #pragma unroll
            for (int r = 0; r < 8; r++) {
                asm volatile(
                    "cp.async.cg.shared.global [%0], [%1], 16;\n" ::
                    "r"(wsaddr + s * STG_BYTES + r * 4096),
                    "l"(wp + (size_t)(s * 8 + r) * E) : "memory");
            }
        }
        asm volatile("cp.async.commit_group;\n" ::: "memory");
    }

    __syncthreads();   // slab ready (overlapped with prologue issue)

    ull acc[M16][2];
    #pragma unroll
    for (int m = 0; m < M16; m++) { acc[m][0] = 0ULL; acc[m][1] = 0ULL; }

    unsigned bufoff = 0;
    #pragma unroll 1
    for (int s = 0; s < NSTG; s++) {
        asm volatile("cp.async.wait_group 2;\n" ::: "memory");

        // consume stage s (8 rows) from buffer bufoff
        #pragma unroll
        for (int r = 0; r < 8; r++) {
            ulonglong2 w = *reinterpret_cast<const ulonglong2*>(
                wstage + bufoff + r * 4096 + tid * 16);
            const ulonglong2* row =
                reinterpret_cast<const ulonglong2*>(sp + (s * 8 + r) * M16);
            #pragma unroll
            for (int q = 0; q < 8; q++) {
                ulonglong2 a = row[q];
                fma2(acc[2*q  ][0], w.x, a.x);
                fma2(acc[2*q  ][1], w.y, a.x);
                fma2(acc[2*q+1][0], w.x, a.y);
                fma2(acc[2*q+1][1], w.y, a.y);
            }
        }

        // refill the buffer just freed with stage s+3
        if (s + NSTAGES < NSTG) {
            #pragma unroll
            for (int r = 0; r < 8; r++) {
                asm volatile(
                    "cp.async.cg.shared.global [%0], [%1], 16;\n" ::
                    "r"(wsaddr + bufoff + r * 4096),
                    "l"(wp + (size_t)((s + NSTAGES) * 8 + r) * E) : "memory");
            }
        }
        asm volatile("cp.async.commit_group;\n" ::: "memory");

        bufoff += STG_BYTES;
        if (bufoff == NSTAGES * STG_BYTES) bufoff = 0;
    }

    size_t base = ((size_t)blockIdx.y * M16) * E + n;
    #pragma unroll
    for (int m = 0; m < M16; m++) {
        ulonglong2 o; o.x = acc[m][0]; o.y = acc[m][1];
        *reinterpret_cast<ulonglong2*>(&partial[base + (size_t)m * E]) = o;
    }
}

// ---- grid-wide sync (all NRBLK CTAs resident: grid < SM count) ----
__device__ __forceinline__ void grid_sync(unsigned* ctr) {
    __syncthreads();
    if (threadIdx.x == 0) {
        __threadfence();
        atomicAdd(ctr, 1u);
        while (atomicAdd(ctr, 0u) < (unsigned)NRBLK) { }
    }
    __syncthreads();
    __threadfence();
}

// ============================================================
// Fused split-K reduce + bias + LN (+ReLU) with internal grid sync.
// grid=(8, 16)=128 blocks, block=256.
// ============================================================
template<bool RELU>
__global__ void __launch_bounds__(256) reduce_apply_kernel(
    const float4* __restrict__ partial4,
    const float4* __restrict__ bias4,
    const float4* __restrict__ gamma4,
    const float4* __restrict__ beta4,
    float4* __restrict__ out4,
    float2* __restrict__ stats,
    unsigned* ctr)
{
    int m    = blockIdx.y;
    int tid  = threadIdx.x;
    int c4   = tid & 127;
    int half = tid >> 7;
    int n4   = blockIdx.x * 128 + c4;

    const float4* p = partial4 + (size_t)m * (E / 4) + n4;
    const size_t stride = (size_t)M16 * (E / 4);

    float4 a[4];
    a[0] = (half == 0) ? bias4[n4] : make_float4(0.f, 0.f, 0.f, 0.f);
    #pragma unroll
    for (int r = 1; r < 4; r++) a[r] = make_float4(0.f, 0.f, 0.f, 0.f);

    int s0 = half * 32;
    #pragma unroll
    for (int ks = 0; ks < 32; ks += 4) {
        #pragma unroll
        for (int r = 0; r < 4; r++) {
            float4 v = __ldcs(&p[(size_t)(s0 + ks + r) * stride]);
            a[r].x += v.x; a[r].y += v.y; a[r].z += v.z; a[r].w += v.w;
        }
    }
    a[0].x += a[1].x; a[0].y += a[1].y; a[0].z += a[1].z; a[0].w += a[1].w;
    a[2].x += a[3].x; a[2].y += a[3].y; a[2].z += a[3].z; a[2].w += a[3].w;
    float4 v;
    v.x = a[0].x + a[2].x; v.y = a[0].y + a[2].y;
    v.z = a[0].z + a[2].z; v.w = a[0].w + a[2].w;

    __shared__ float4 buf[128];
    __shared__ float rs[128], rq[128];
    if (half == 1) buf[c4] = v;
    __syncthreads();
    if (half == 0) {
        float4 o = buf[c4];
        v.x += o.x; v.y += o.y; v.z += o.z; v.w += o.w;
        rs[c4] = (v.x + v.y) + (v.z + v.w);
        rq[c4] = (v.x * v.x + v.y * v.y) + (v.z * v.z + v.w * v.w);
    }
    __syncthreads();
    for (int off = 64; off > 0; off >>= 1) {
        if (tid < off) { rs[tid] += rs[tid + off]; rq[tid] += rq[tid + off]; }
        __syncthreads();
    }
    if (tid == 0)
        stats[m * 8 + blockIdx.x] = make_float2(rs[0], rq[0]);

    grid_sync(ctr);

    if (half == 0) {
        float sum = 0.f, sq = 0.f;
        #pragma unroll
        for (int c = 0; c < 8; c++) {
            float2 s = __ldcg(&stats[m * 8 + c]);
            sum += s.x; sq += s.y;
        }
        float mu   = sum * (1.0f / E);
        float var  = sq * (1.0f / E) - mu * mu;
        float rstd = rsqrtf(var + LN_EPS);

        float4 g = gamma4[n4];
        float4 b = beta4[n4];
        float4 y;
        y.x = (v.x - mu) * rstd * g.x + b.x;
        y.y = (v.y - mu) * rstd * g.y + b.y;
        y.z = (v.z - mu) * rstd * g.z + b.z;
        y.w = (v.w - mu) * rstd * g.w + b.w;
        if (RELU) {
            y.x = fmaxf(y.x, 0.f); y.y = fmaxf(y.y, 0.f);
            y.z = fmaxf(y.z, 0.f); y.w = fmaxf(y.w, 0.f);
        }
        out4[(size_t)m * (E / 4) + n4] = y;
    }
}

// ============================================================
// launcher — 5 launches
// ============================================================
extern "C" void kernel_launch(void* const* d_in, const int* in_sizes, int n_in,
                              void* d_out, int out_size)
{
    const float* emb = (const float*)d_in[0];
    const float* W1  = (const float*)d_in[1];
    const float* b1  = (const float*)d_in[2];
    const float* g1  = (const float*)d_in[3];
    const float* be1 = (const float*)d_in[4];
    const float* W2  = (const float*)d_in[5];
    const float* b2  = (const float*)d_in[6];
    const float* g2  = (const float*)d_in[7];
    const float* be2 = (const float*)d_in[8];
    const int*   bp  = (const int*)d_in[9];

    float* out = (float*)d_out;
    float* out_joint = out;                      // [17][4096]
    float* out_bone  = out + (size_t)J * E;      // [16][4096]

    float*    h_p;       cudaGetSymbolAddress((void**)&h_p, d_h);
    float*    partial_p; cudaGetSymbolAddress((void**)&partial_p, d_partial);
    float2*   stats_p;   cudaGetSymbolAddress((void**)&stats_p, d_stats);
    unsigned* ctr_p;     cudaGetSymbolAddress((void**)&ctr_p, d_ctr);

    const int smem1 = TK1 * M16 * 8 + NSTAGES * STG_BYTES;  // 112 KB
    const int smem2 = TK2 * M16 * 8 + NSTAGES * STG_BYTES;  // 104 KB
    cudaFuncSetAttribute(gemm_splitk<TK1, 0>,
        cudaFuncAttributeMaxDynamicSharedMemorySize, smem1);
    cudaFuncSetAttribute(gemm_splitk<TK2, 1>,
        cudaFuncAttributeMaxDynamicSharedMemorySize, smem2);

    // 1. normalize joints -> output head (+ zero sync counters)
    normalize_kernel<<<J, 256>>>(emb, out_joint);

    // 2. GEMM1 (pair gather fused)
    gemm_splitk<TK1, 0><<<dim3(4, K1 / TK1), 256, smem1>>>(
        W1, out_joint, bp, partial_p);

    // 3. fused reduce + LN + ReLU -> h
    reduce_apply_kernel<true><<<dim3(8, M16), 256>>>(
        (const float4*)partial_p, (const float4*)b1,
        (const float4*)g1, (const float4*)be1,
        (float4*)h_p, stats_p, ctr_p + 0);

    // 4. GEMM2 (h gather fused)  — grid MUST be (4, 64) to match indexing
    gemm_splitk<TK2, 1><<<dim3(4, K2 / TK2), 256, smem2>>>(
        W2, h_p, nullptr, partial_p);

    // 5. fused reduce + LN -> bone features
    reduce_apply_kernel<false><<<dim3(8, M16), 256>>>(
        (const float4*)partial_p, (const float4*)b2,
        (const float4*)g2, (const float4*)be2,
        (float4*)out_bone, stats_p, ctr_p + 1);
}